// round 2
// baseline (speedup 1.0000x reference)
#include <cuda_runtime.h>
#include <cuda_bf16.h>
#include <cstdint>

#define T_LEN 4096
#define DEMB  256
#define HDIM  256
#define NGATE 1024          // 4*HDIM
#define TAGS  32
#define STARTT 30
#define STOPT  31
#define NEGV  (-10000.0f)

// ---------------- scratch (static device globals; no allocation) ----------------
__device__ __align__(16) float g_x[(size_t)T_LEN * DEMB];               // 4 MB
__device__ __align__(16) float g_xg[(size_t)2 * T_LEN * NGATE];         // 32 MB
__device__ __align__(16) float g_hs[(size_t)2 * T_LEN * HDIM];          // 8 MB
__device__ __align__(16) float g_feats[(size_t)T_LEN * TAGS];           // 512 KB

// ---------------- small helpers ----------------
__device__ __forceinline__ float sigf(float x)   { return 1.0f / (1.0f + __expf(-x)); }
__device__ __forceinline__ float tanh_f(float x) { return 1.0f - 2.0f / (__expf(2.0f * x) + 1.0f); }

__device__ __forceinline__ unsigned cluster_rank() {
    unsigned r; asm("mov.u32 %0, %%cluster_ctarank;" : "=r"(r)); return r;
}
__device__ __forceinline__ void cluster_sync_() {
    asm volatile("barrier.cluster.arrive.aligned;\n\tbarrier.cluster.wait.aligned;" ::: "memory");
}
// store float into the SAME smem offset of cluster CTA r (release happens at cluster arrive)
__device__ __forceinline__ void st_cluster_f32(const float* local_generic, int r, float v) {
    uint32_t saddr = (uint32_t)__cvta_generic_to_shared((void*)local_generic);
    uint32_t daddr;
    asm("mapa.shared::cluster.u32 %0, %1, %2;" : "=r"(daddr) : "r"(saddr), "r"(r));
    asm volatile("st.shared::cluster.f32 [%0], %1;" :: "r"(daddr), "f"(v) : "memory");
}

// ---------------- phase 1a: embedding gather ----------------
__global__ __launch_bounds__(256) void k_embed(const int* __restrict__ seq,
                                               const float* __restrict__ E) {
    int t = blockIdx.x;
    int d = threadIdx.x;
    g_x[(size_t)t * DEMB + d] = E[(size_t)seq[t] * DEMB + d];
}

// ---------------- phase 1b: input projections xg = x @ Wih^T + (bih+bhh) ----------------
// C[t, n] for n in [0,1024), dirs in z. Tiles: BM=64 (t), BN=64 (n), BK=16, 256 thr, 4x4/thread
__global__ __launch_bounds__(256) void k_xg(const float* __restrict__ WihF,
                                            const float* __restrict__ WihB,
                                            const float* __restrict__ bihF,
                                            const float* __restrict__ bhhF,
                                            const float* __restrict__ bihB,
                                            const float* __restrict__ bhhB) {
    const int BM = 64, BN = 64, BK = 16, PAD = 4;
    __shared__ __align__(16) float sA[BK][BM + PAD];
    __shared__ __align__(16) float sB[BK][BN + PAD];

    const int dir = blockIdx.z;
    const float* __restrict__ W  = dir ? WihB : WihF;
    const float* __restrict__ b1 = dir ? bihB : bihF;
    const float* __restrict__ b2 = dir ? bhhB : bhhF;

    const int n0 = blockIdx.x * BN;
    const int t0 = blockIdx.y * BM;
    const int tid = threadIdx.x;
    const int tx = tid & 15, ty = tid >> 4;
    const int lm = tid >> 2, lq = tid & 3;   // loader: row, quad-of-4-floats

    float acc[4][4];
#pragma unroll
    for (int i = 0; i < 4; i++)
#pragma unroll
        for (int j = 0; j < 4; j++) acc[i][j] = 0.0f;

    for (int k0 = 0; k0 < DEMB; k0 += BK) {
        float4 av = *reinterpret_cast<const float4*>(&g_x[(size_t)(t0 + lm) * DEMB + k0 + lq * 4]);
        float4 bv = *reinterpret_cast<const float4*>(&W[(size_t)(n0 + lm) * DEMB + k0 + lq * 4]);
        sA[lq * 4 + 0][lm] = av.x; sA[lq * 4 + 1][lm] = av.y;
        sA[lq * 4 + 2][lm] = av.z; sA[lq * 4 + 3][lm] = av.w;
        sB[lq * 4 + 0][lm] = bv.x; sB[lq * 4 + 1][lm] = bv.y;
        sB[lq * 4 + 2][lm] = bv.z; sB[lq * 4 + 3][lm] = bv.w;
        __syncthreads();
#pragma unroll
        for (int kk = 0; kk < BK; kk++) {
            float4 a4 = *reinterpret_cast<const float4*>(&sA[kk][ty * 4]);
            float4 b4 = *reinterpret_cast<const float4*>(&sB[kk][tx * 4]);
            float a[4] = {a4.x, a4.y, a4.z, a4.w};
            float b[4] = {b4.x, b4.y, b4.z, b4.w};
#pragma unroll
            for (int i = 0; i < 4; i++)
#pragma unroll
                for (int j = 0; j < 4; j++) acc[i][j] += a[i] * b[j];
        }
        __syncthreads();
    }
#pragma unroll
    for (int i = 0; i < 4; i++) {
        int row = t0 + ty * 4 + i;
#pragma unroll
        for (int j = 0; j < 4; j++) {
            int col = n0 + tx * 4 + j;
            g_xg[((size_t)dir * T_LEN + row) * NGATE + col] = acc[i][j] + b1[col] + b2[col];
        }
    }
}

// ---------------- phase 2: recurrence. 2 clusters (one per direction) x 8 CTAs x 256 thr ----
// CTA r of a cluster owns hidden units [32r, 32r+32): 128 gate rows, weights in registers
// (2 threads per row, 128 cols each; warps 2g/2g+1 handle gate-group g so LDS is broadcast).
__global__ __launch_bounds__(256, 1) __cluster_dims__(8, 1, 1)
void k_rec(const float* __restrict__ WhhF, const float* __restrict__ WhhB,
           const float* __restrict__ h0,   const float* __restrict__ c0) {
    __shared__ __align__(16) float h_sh[2][HDIM];
    __shared__ float part_sh[128];
    __shared__ float gates_sh[128];

    const int rank = (int)cluster_rank();
    const int dir  = (int)(blockIdx.x >> 3);

    const int tid  = threadIdx.x;
    const int warp = tid >> 5, lane = tid & 31;
    const int lr   = (warp >> 1) * 32 + lane;   // local row 0..127
    const int half = warp & 1;                   // which 128-col half of the dot
    const int gate = lr >> 5;                    // 0..3 (i,f,g,o)
    const int unit = rank * 32 + (lr & 31);      // global hidden unit 0..255
    const int grow = gate * HDIM + unit;         // global gate row 0..1023

    const float* __restrict__ Whh = dir ? WhhB : WhhF;

    // register-resident weights: 128 floats
    float w[128];
    {
        const float4* wp = reinterpret_cast<const float4*>(Whh + (size_t)grow * HDIM + half * 128);
#pragma unroll
        for (int k = 0; k < 32; k++) {
            float4 v = wp[k];
            w[4 * k + 0] = v.x; w[4 * k + 1] = v.y; w[4 * k + 2] = v.z; w[4 * k + 3] = v.w;
        }
    }

    h_sh[0][tid] = h0[dir * HDIM + tid];
    float c = 0.0f;
    if (warp == 0) c = c0[dir * HDIM + unit];
    __syncthreads();
    cluster_sync_();

    const float* __restrict__ xgbase = g_xg + (size_t)dir * T_LEN * NGATE + grow;
    float xg_next = 0.0f;
    if (half == 0) {
        int t0 = dir ? (T_LEN - 1) : 0;
        xg_next = __ldg(xgbase + (size_t)t0 * NGATE);
    }

    int cur = 0;
    for (int s = 0; s < T_LEN; s++) {
        const int t = dir ? (T_LEN - 1 - s) : s;
        const float xg_cur = xg_next;
        if (half == 0 && s + 1 < T_LEN) {
            int tn = dir ? (T_LEN - 2 - s) : (s + 1);
            xg_next = __ldg(xgbase + (size_t)tn * NGATE);
        }

        const float* hrow = &h_sh[cur][half * 128];
        float a0 = 0.f, a1 = 0.f, a2 = 0.f, a3 = 0.f;
#pragma unroll
        for (int k = 0; k < 128; k += 4) {
            float4 hv = *reinterpret_cast<const float4*>(hrow + k);
            a0 += w[k + 0] * hv.x; a1 += w[k + 1] * hv.y;
            a2 += w[k + 2] * hv.z; a3 += w[k + 3] * hv.w;
        }
        float acc = (a0 + a1) + (a2 + a3);

        if (half) part_sh[lr] = acc;
        __syncthreads();
        if (!half) gates_sh[lr] = acc + part_sh[lr] + xg_cur;
        __syncthreads();

        if (warp == 0) {
            float gi = gates_sh[lane];
            float gf = gates_sh[32 + lane];
            float gg = gates_sh[64 + lane];
            float go = gates_sh[96 + lane];
            float ii = sigf(gi), ff = sigf(gf), tg = tanh_f(gg), oo = sigf(go);
            c = ff * c + ii * tg;
            float h = oo * tanh_f(c);
            const float* nb = &h_sh[cur ^ 1][unit];
#pragma unroll
            for (int r = 0; r < 8; r++) st_cluster_f32(nb, r, h);
            g_hs[((size_t)dir * T_LEN + t) * HDIM + unit] = h;
        }
        cluster_sync_();
        cur ^= 1;
    }
}

// ---------------- phase 3: feats[t,k] = [hf(t);hb(t)] . W_out[k] + b_out[k] ----------------
__global__ __launch_bounds__(256) void k_feats(const float* __restrict__ Wout,
                                               const float* __restrict__ bout) {
    const int k  = threadIdx.x & 31;
    const int tl = threadIdx.x >> 5;         // 0..7
    const int t  = blockIdx.x * 8 + tl;
    const float4* hf = reinterpret_cast<const float4*>(g_hs + (size_t)t * HDIM);
    const float4* hb = reinterpret_cast<const float4*>(g_hs + (size_t)T_LEN * HDIM + (size_t)t * HDIM);
    const float4* wr = reinterpret_cast<const float4*>(Wout + (size_t)k * 512);
    float acc = bout[k];
#pragma unroll 8
    for (int d = 0; d < 64; d++) {
        float4 h4 = hf[d]; float4 w4 = wr[d];
        acc += h4.x * w4.x + h4.y * w4.y + h4.z * w4.z + h4.w * w4.w;
    }
#pragma unroll 8
    for (int d = 0; d < 64; d++) {
        float4 h4 = hb[d]; float4 w4 = wr[64 + d];
        acc += h4.x * w4.x + h4.y * w4.y + h4.z * w4.z + h4.w * w4.w;
    }
    g_feats[(size_t)t * TAGS + k] = acc;
}

// ---------------- phase 4: Viterbi forward + backtrace (1 warp; bps in dyn smem) -----------
__global__ void k_viterbi(const float* __restrict__ trans, float* __restrict__ out,
                          int out_size) {
    extern __shared__ unsigned char bps[];   // T_LEN * 32 bytes
    const int lane = threadIdx.x;

    float tr[TAGS];
#pragma unroll
    for (int p = 0; p < TAGS; p++) tr[p] = trans[lane * TAGS + p];   // trans[next=lane][prev=p]
    const float trs = trans[STOPT * TAGS + lane];                     // trans[STOP][lane]

    float fv = (lane == STARTT) ? 0.0f : NEGV;
    float fnext = g_feats[lane];
    for (int t = 0; t < T_LEN; t++) {
        const float feat = fnext;
        if (t + 1 < T_LEN) fnext = g_feats[(size_t)(t + 1) * TAGS + lane];
        float best = -3.4e38f; int bi = 0;
#pragma unroll
        for (int p = 0; p < TAGS; p++) {
            float s = __shfl_sync(0xffffffffu, fv, p) + tr[p];
            if (s > best) { best = s; bi = p; }   // strict > keeps first index (jnp.argmax)
        }
        fv = best + feat;
        bps[(size_t)t * TAGS + lane] = (unsigned char)bi;
    }
    __syncwarp();

    float bv = fv + trs; int bidx = lane;
#pragma unroll
    for (int off = 16; off; off >>= 1) {
        float ov = __shfl_down_sync(0xffffffffu, bv, off);
        int   oi = __shfl_down_sync(0xffffffffu, bidx, off);
        if (ov > bv || (ov == bv && oi < bidx)) { bv = ov; bidx = oi; }
    }
    if (lane == 0) {
        const int off = (out_size > T_LEN) ? 1 : 0;   // [score, path...] vs path-only
        if (off) out[0] = bv;
        int b = bidx;
        out[off + T_LEN - 1] = (float)b;
        for (int t = T_LEN - 1; t >= 1; --t) {
            b = (int)bps[(size_t)t * TAGS + b];
            out[off + t - 1] = (float)b;
        }
    }
}

// ---------------- launch ----------------
extern "C" void kernel_launch(void* const* d_in, const int* in_sizes, int n_in,
                              void* d_out, int out_size) {
    (void)in_sizes; (void)n_in;
    const int*   seq   = (const int*)  d_in[0];
    const float* E     = (const float*)d_in[1];
    const float* WihF  = (const float*)d_in[2];
    const float* WhhF  = (const float*)d_in[3];
    const float* bihF  = (const float*)d_in[4];
    const float* bhhF  = (const float*)d_in[5];
    const float* WihB  = (const float*)d_in[6];
    const float* WhhB  = (const float*)d_in[7];
    const float* bihB  = (const float*)d_in[8];
    const float* bhhB  = (const float*)d_in[9];
    const float* h0    = (const float*)d_in[10];
    const float* c0    = (const float*)d_in[11];
    const float* Wout  = (const float*)d_in[12];
    const float* bout  = (const float*)d_in[13];
    const float* trans = (const float*)d_in[14];
    float* out = (float*)d_out;

    k_embed<<<T_LEN, 256>>>(seq, E);
    dim3 gg(NGATE / 64, T_LEN / 64, 2);
    k_xg<<<gg, 256>>>(WihF, WihB, bihF, bhhF, bihB, bhhB);
    k_rec<<<16, 256>>>(WhhF, WhhB, h0, c0);
    k_feats<<<T_LEN / 8, 256>>>(Wout, bout);
    cudaFuncSetAttribute(k_viterbi, cudaFuncAttributeMaxDynamicSharedMemorySize,
                         T_LEN * TAGS);
    k_viterbi<<<1, 32, T_LEN * TAGS>>>(trans, out, out_size);
}